// round 2
// baseline (speedup 1.0000x reference)
#include <cuda_runtime.h>

// TpsGridGen: theta (64, 50) -> grid (64, 256, 192, 2) fp32
// Single fused kernel:
//   Phase A: per-block cooperative coefficient solve  [W;A] = Li[:, :25] @ (theta+P)
//            (Li = inv(L) computed entirely at COMPILE TIME: constexpr fp64
//             Gauss-Jordan with partial pivoting + constexpr log)
//   Phase B: per-pixel RBF evaluation with packed fma.rn.f32x2 over 28
//            coefficient (x,y) pairs for 32 batches.

#define OUT_H 256
#define OUT_W 192
#define NCP   25
#define NB    64
#define NCOEF 28   // 25 RBF + [1, gx, gy] affine

// ---------------------------------------------------------------------------
// Compile-time constants
// ---------------------------------------------------------------------------
struct TPSConst {
    float li[NCOEF][NCP];
    float px[NCP];
    float py[NCP];
};

constexpr double cfabs(double x) { return x < 0.0 ? -x : x; }

constexpr double clog(double x) {
    int e = 0;
    while (x >= 1.4142135623730951) { x *= 0.5; e++; }
    while (x <  0.7071067811865476) { x *= 2.0; e--; }
    double t  = (x - 1.0) / (x + 1.0);
    double t2 = t * t;
    double p = t, s = 0.0;
    for (int k = 0; k < 27; k++) { s += p / (double)(2 * k + 1); p *= t2; }
    return 2.0 * s + (double)e * 0.6931471805599453094172321214581766;
}

constexpr TPSConst make_tps() {
    TPSConst r{};
    const double ax[5] = {-1.0, -0.5, 0.0, 0.5, 1.0};
    double PX[NCP] = {}, PY[NCP] = {};
    for (int i = 0; i < 5; i++)
        for (int j = 0; j < 5; j++) { PX[i * 5 + j] = ax[i]; PY[i * 5 + j] = ax[j]; }

    double a[28][56] = {};
    for (int i = 0; i < 25; i++)
        for (int j = 0; j < 25; j++) {
            if (i == j) { a[i][j] = 0.0; }
            else {
                double dx = PX[i] - PX[j], dy = PY[i] - PY[j];
                double d2 = dx * dx + dy * dy;
                a[i][j] = d2 * clog(d2);
            }
        }
    for (int i = 0; i < 25; i++) {
        a[i][25] = 1.0; a[i][26] = PX[i]; a[i][27] = PY[i];
        a[25][i] = 1.0; a[26][i] = PX[i]; a[27][i] = PY[i];
    }
    for (int i = 0; i < 28; i++) a[i][28 + i] = 1.0;

    for (int k = 0; k < 28; k++) {
        int piv = k; double best = cfabs(a[k][k]);
        for (int i = k + 1; i < 28; i++) {
            double v = cfabs(a[i][k]);
            if (v > best) { best = v; piv = i; }
        }
        if (piv != k)
            for (int j = 0; j < 56; j++) {
                double tmp = a[k][j]; a[k][j] = a[piv][j]; a[piv][j] = tmp;
            }
        double inv = 1.0 / a[k][k];
        for (int j = 0; j < 56; j++) a[k][j] *= inv;
        for (int i = 0; i < 28; i++) {
            if (i == k) continue;
            double f = a[i][k];
            if (f != 0.0)
                for (int j = 0; j < 56; j++) a[i][j] -= f * a[k][j];
        }
    }
    for (int n = 0; n < NCOEF; n++)
        for (int m = 0; m < NCP; m++)
            r.li[n][m] = (float)a[n][28 + m];
    for (int i = 0; i < NCP; i++) { r.px[i] = (float)PX[i]; r.py[i] = (float)PY[i]; }
    return r;
}

constexpr TPSConst H_TPS = make_tps();
__constant__ TPSConst c_tps = H_TPS;

// Transposed + lane-duplicated Li for the cooperative coef solve.
// v[m][part][j] = (li[part*7+j][m], li[part*7+j][m]); padded j-dim to 8 so each
// (m,part) row is 64B-aligned for vectorized LDG.
struct alignas(16) TPSLi2 { float2 v[NCP][4][8]; };

constexpr TPSLi2 make_li2() {
    TPSLi2 r{};
    TPSConst t = make_tps();
    for (int m = 0; m < NCP; m++)
        for (int part = 0; part < 4; part++)
            for (int j = 0; j < 7; j++) {
                float v = t.li[part * 7 + j][m];
                r.v[m][part][j] = float2{v, v};
            }
    return r;
}

__device__ const TPSLi2 d_li2 = make_li2();

// ---------------------------------------------------------------------------
// Packed f32x2 helpers
// ---------------------------------------------------------------------------
__device__ __forceinline__ unsigned long long pack2(float lo, float hi) {
    unsigned long long r;
    asm("mov.b64 %0, {%1, %2};" : "=l"(r) : "f"(lo), "f"(hi));
    return r;
}
__device__ __forceinline__ unsigned long long fma2(unsigned long long a,
                                                   unsigned long long b,
                                                   unsigned long long c) {
    unsigned long long d;
    asm("fma.rn.f32x2 %0, %1, %2, %3;" : "=l"(d) : "l"(a), "l"(b), "l"(c));
    return d;
}

// ---------------------------------------------------------------------------
// Fused kernel. grid (384, 2), block 128. Each thread: 1 pixel x 32 batches.
// ---------------------------------------------------------------------------
__global__ __launch_bounds__(128, 6) void tps_fused_kernel(
    const float* __restrict__ theta, float2* __restrict__ out) {

    // One buffer, two lives: Q (32x25 float2) during the solve, then coefs
    // (32x28 float2) for the main loop. 7.2 KB -> smem never limits occupancy.
    __shared__ __align__(16) float2 sbuf[32 * NCOEF];

    const int tid   = threadIdx.x;
    const int half  = blockIdx.y;          // which 32-batch half
    const int bbase = half * 32;

    // ---- Phase A1: stage Q = theta + P for this half's 32 batches ----
    for (int i = tid; i < 32 * NCP; i += 128) {
        const int b = i / NCP;
        const int m = i - b * NCP;
        const float* t = theta + (bbase + b) * (2 * NCP);
        sbuf[i] = make_float2(t[m] + c_tps.px[m], t[NCP + m] + c_tps.py[m]);
    }
    __syncthreads();

    // ---- Phase A2: coefficient solve. thread -> (batch b, coef quarter) ----
    unsigned long long acc[7];
    {
        const int b    = tid >> 2;
        const int part = tid & 3;
#pragma unroll
        for (int j = 0; j < 7; j++) acc[j] = 0ull;
        const float2* qrow = sbuf + b * NCP;
#pragma unroll
        for (int m = 0; m < NCP; m++) {
            unsigned long long q2 = *(const unsigned long long*)(qrow + m);
            const float2* lrow = &d_li2.v[m][part][0];
            const ulonglong2* lp = (const ulonglong2*)lrow;
            const ulonglong2 l01 = lp[0];
            const ulonglong2 l23 = lp[1];
            const ulonglong2 l45 = lp[2];
            const unsigned long long l6 = ((const unsigned long long*)lrow)[6];
            acc[0] = fma2(l01.x, q2, acc[0]);
            acc[1] = fma2(l01.y, q2, acc[1]);
            acc[2] = fma2(l23.x, q2, acc[2]);
            acc[3] = fma2(l23.y, q2, acc[3]);
            acc[4] = fma2(l45.x, q2, acc[4]);
            acc[5] = fma2(l45.y, q2, acc[5]);
            acc[6] = fma2(l6,    q2, acc[6]);
        }
    }
    __syncthreads();   // all Q reads complete before sbuf is repurposed
    {
        const int b    = tid >> 2;
        const int part = tid & 3;
        unsigned long long* dst =
            (unsigned long long*)(sbuf + b * NCOEF + part * 7);
#pragma unroll
        for (int j = 0; j < 7; j++) dst[j] = acc[j];
    }

    // ---- Phase B prep: per-pixel RBF vector (independent of smem) ----
    const int pid = blockIdx.x * 128 + tid;
    const int h = pid / OUT_W;
    const int w = pid - h * OUT_W;

    const float gx = (w == OUT_W - 1) ? 1.0f
                     : (float)(-1.0 + (double)w * (2.0 / (double)(OUT_W - 1)));
    const float gy = (h == OUT_H - 1) ? 1.0f
                     : (float)(-1.0 + (double)h * (2.0 / (double)(OUT_H - 1)));

    unsigned long long U2[NCOEF];
#pragma unroll
    for (int n = 0; n < NCP; n++) {
        const float dx = gx - c_tps.px[n];
        const float dy = gy - c_tps.py[n];
        const float d2 = dx * dx + dy * dy;
        const float u = (d2 == 0.0f) ? 0.0f : d2 * __logf(d2);
        U2[n] = pack2(u, u);
    }
    U2[25] = pack2(1.0f, 1.0f);
    U2[26] = pack2(gx, gx);
    U2[27] = pack2(gy, gy);

    __syncthreads();   // coefs visible

    // ---- Phase B: accumulate 32 batches, 2 at a time ----
    for (int bl = 0; bl < 32; bl += 2) {
        const ulonglong2* c0 = (const ulonglong2*)(sbuf + (bl)     * NCOEF);
        const ulonglong2* c1 = (const ulonglong2*)(sbuf + (bl + 1) * NCOEF);
        unsigned long long a0 = 0ull, a1 = 0ull;
#pragma unroll
        for (int q = 0; q < NCOEF / 2; q++) {
            const ulonglong2 p0 = c0[q];
            const ulonglong2 p1 = c1[q];
            a0 = fma2(U2[2 * q],     p0.x, a0);
            a0 = fma2(U2[2 * q + 1], p0.y, a0);
            a1 = fma2(U2[2 * q],     p1.x, a1);
            a1 = fma2(U2[2 * q + 1], p1.y, a1);
        }
        const int b0 = bbase + bl;
        float2 r0, r1;
        asm("mov.b64 {%0, %1}, %2;" : "=f"(r0.x), "=f"(r0.y) : "l"(a0));
        asm("mov.b64 {%0, %1}, %2;" : "=f"(r1.x), "=f"(r1.y) : "l"(a1));
        out[(size_t)(b0 * OUT_H + h) * OUT_W + w]       = r0;
        out[(size_t)((b0 + 1) * OUT_H + h) * OUT_W + w] = r1;
    }
}

// ---------------------------------------------------------------------------
extern "C" void kernel_launch(void* const* d_in, const int* in_sizes, int n_in,
                              void* d_out, int out_size) {
    const float* theta = (const float*)d_in[0];
    (void)in_sizes; (void)n_in; (void)out_size;

    dim3 grid(OUT_H * OUT_W / 128, 2);
    tps_fused_kernel<<<grid, 128>>>(theta, (float2*)d_out);
}

// round 3
// speedup vs baseline: 1.4465x; 1.4465x over previous
#include <cuda_runtime.h>

// TpsGridGen: theta (64, 50) -> grid (64, 256, 192, 2) fp32
// Single fused kernel:
//   Phase A: per-block coefficient solve [W;A] = Li[:,:25] @ (theta+P).
//            Li lives in __constant__; the coef-quarter index is the WARP id,
//            so every Li access is runtime-uniform -> constant-cache broadcast.
//   Phase B: per-pixel RBF evaluation, packed fma.rn.f32x2 over 28 (x,y)
//            coefficient pairs x 32 batches (R1-proven inner loop).

#define OUT_H 256
#define OUT_W 192
#define NCP   25
#define NB    64
#define NCOEF 28   // 25 RBF + [1, gx, gy] affine

// ---------------------------------------------------------------------------
// Compile-time constants (constexpr fp64 Gauss-Jordan w/ pivoting + clog)
// ---------------------------------------------------------------------------
struct TPSConst {
    float li[NCOEF][NCP];
    float px[NCP];
    float py[NCP];
};

constexpr double cfabs(double x) { return x < 0.0 ? -x : x; }

constexpr double clog(double x) {
    int e = 0;
    while (x >= 1.4142135623730951) { x *= 0.5; e++; }
    while (x <  0.7071067811865476) { x *= 2.0; e--; }
    double t  = (x - 1.0) / (x + 1.0);
    double t2 = t * t;
    double p = t, s = 0.0;
    for (int k = 0; k < 27; k++) { s += p / (double)(2 * k + 1); p *= t2; }
    return 2.0 * s + (double)e * 0.6931471805599453094172321214581766;
}

constexpr TPSConst make_tps() {
    TPSConst r{};
    const double ax[5] = {-1.0, -0.5, 0.0, 0.5, 1.0};
    double PX[NCP] = {}, PY[NCP] = {};
    for (int i = 0; i < 5; i++)
        for (int j = 0; j < 5; j++) { PX[i * 5 + j] = ax[i]; PY[i * 5 + j] = ax[j]; }

    double a[28][56] = {};
    for (int i = 0; i < 25; i++)
        for (int j = 0; j < 25; j++) {
            if (i == j) { a[i][j] = 0.0; }
            else {
                double dx = PX[i] - PX[j], dy = PY[i] - PY[j];
                double d2 = dx * dx + dy * dy;
                a[i][j] = d2 * clog(d2);
            }
        }
    for (int i = 0; i < 25; i++) {
        a[i][25] = 1.0; a[i][26] = PX[i]; a[i][27] = PY[i];
        a[25][i] = 1.0; a[26][i] = PX[i]; a[27][i] = PY[i];
    }
    for (int i = 0; i < 28; i++) a[i][28 + i] = 1.0;

    for (int k = 0; k < 28; k++) {
        int piv = k; double best = cfabs(a[k][k]);
        for (int i = k + 1; i < 28; i++) {
            double v = cfabs(a[i][k]);
            if (v > best) { best = v; piv = i; }
        }
        if (piv != k)
            for (int j = 0; j < 56; j++) {
                double tmp = a[k][j]; a[k][j] = a[piv][j]; a[piv][j] = tmp;
            }
        double inv = 1.0 / a[k][k];
        for (int j = 0; j < 56; j++) a[k][j] *= inv;
        for (int i = 0; i < 28; i++) {
            if (i == k) continue;
            double f = a[i][k];
            if (f != 0.0)
                for (int j = 0; j < 56; j++) a[i][j] -= f * a[k][j];
        }
    }
    for (int n = 0; n < NCOEF; n++)
        for (int m = 0; m < NCP; m++)
            r.li[n][m] = (float)a[n][28 + m];
    for (int i = 0; i < NCP; i++) { r.px[i] = (float)PX[i]; r.py[i] = (float)PY[i]; }
    return r;
}

constexpr TPSConst H_TPS = make_tps();
__constant__ TPSConst c_tps = H_TPS;

// Transposed + lane-duplicated Li for phase A, in __constant__.
// v[m][part][j] = dup(li[part*7+j][m]); j padded to 8 for 16B alignment.
// Accessed with part == warp id -> runtime-uniform -> const-cache broadcast.
struct alignas(16) TPSLi2 { float2 v[NCP][4][8]; };

constexpr TPSLi2 make_li2() {
    TPSLi2 r{};
    TPSConst t = make_tps();
    for (int m = 0; m < NCP; m++)
        for (int part = 0; part < 4; part++)
            for (int j = 0; j < 7; j++) {
                float v = t.li[part * 7 + j][m];
                r.v[m][part][j] = float2{v, v};
            }
    return r;
}

__constant__ TPSLi2 c_li2 = make_li2();

// ---------------------------------------------------------------------------
// Packed f32x2 helpers
// ---------------------------------------------------------------------------
__device__ __forceinline__ unsigned long long pack2(float lo, float hi) {
    unsigned long long r;
    asm("mov.b64 %0, {%1, %2};" : "=l"(r) : "f"(lo), "f"(hi));
    return r;
}
__device__ __forceinline__ unsigned long long fma2(unsigned long long a,
                                                   unsigned long long b,
                                                   unsigned long long c) {
    unsigned long long d;
    asm("fma.rn.f32x2 %0, %1, %2, %3;" : "=l"(d) : "l"(a), "l"(b), "l"(c));
    return d;
}

// ---------------------------------------------------------------------------
// Fused kernel. grid (384, 2), block 128, 5 blocks/SM -> 1.04 waves.
// Each thread: 1 pixel x 32 batches.
// ---------------------------------------------------------------------------
__global__ __launch_bounds__(128, 5) void tps_fused_kernel(
    const float* __restrict__ theta, float2* __restrict__ out) {

    // One buffer, two lives: raw theta floats (32x50 = 6.4 KB) during the
    // solve, then coef pairs (32x28 float2 = 7.2 KB) for the main loop.
    __shared__ __align__(16) float sbuf[32 * NCOEF * 2];

    const int tid   = threadIdx.x;
    const int half  = blockIdx.y;          // which 32-batch half
    const int bbase = half * 32;

    // ---- Phase A1: coalesced stage of this half's theta (1600 floats) ----
    {
        const float4* src = (const float4*)(theta + half * 32 * 2 * NCP);
        float4* dst = (float4*)sbuf;
#pragma unroll
        for (int i = tid; i < 32 * 2 * NCP / 4; i += 128) dst[i] = src[i];
    }
    __syncthreads();

    // ---- Phase A2: coef solve. lane = batch, warp = coef quarter ----
    unsigned long long acc[7];
    {
        const int b    = tid & 31;         // lane -> batch
        const int part = tid >> 5;         // warp -> coef quarter (uniform!)
#pragma unroll
        for (int j = 0; j < 7; j++) acc[j] = 0ull;
        const float* trow = sbuf + b * (2 * NCP);
#pragma unroll
        for (int m = 0; m < NCP; m++) {
            const unsigned long long q2 =
                pack2(trow[m] + c_tps.px[m], trow[NCP + m] + c_tps.py[m]);
            const float2* lrow = &c_li2.v[m][part][0];  // warp-uniform addr
#pragma unroll
            for (int j = 0; j < 7; j++)
                acc[j] = fma2(*(const unsigned long long*)(lrow + j), q2, acc[j]);
        }
    }
    __syncthreads();   // all theta reads complete before sbuf is repurposed
    {
        const int b    = tid & 31;
        const int part = tid >> 5;
        unsigned long long* dst =
            (unsigned long long*)((float2*)sbuf + b * NCOEF + part * 7);
#pragma unroll
        for (int j = 0; j < 7; j++) dst[j] = acc[j];
    }

    // ---- Phase B prep: per-pixel RBF vector ----
    const int pid = blockIdx.x * 128 + tid;
    const int h = pid / OUT_W;
    const int w = pid - h * OUT_W;

    const float gx = (w == OUT_W - 1) ? 1.0f
                     : (float)(-1.0 + (double)w * (2.0 / (double)(OUT_W - 1)));
    const float gy = (h == OUT_H - 1) ? 1.0f
                     : (float)(-1.0 + (double)h * (2.0 / (double)(OUT_H - 1)));

    unsigned long long U2[NCOEF];
#pragma unroll
    for (int n = 0; n < NCP; n++) {
        const float dx = gx - c_tps.px[n];
        const float dy = gy - c_tps.py[n];
        const float d2 = dx * dx + dy * dy;
        const float u = (d2 == 0.0f) ? 0.0f : d2 * __logf(d2);
        U2[n] = pack2(u, u);
    }
    U2[25] = pack2(1.0f, 1.0f);
    U2[26] = pack2(gx, gx);
    U2[27] = pack2(gy, gy);

    __syncthreads();   // coefs visible

    // ---- Phase B: accumulate 32 batches, 2 at a time ----
    const float2* sc = (const float2*)sbuf;
    for (int bl = 0; bl < 32; bl += 2) {
        const ulonglong2* c0 = (const ulonglong2*)(sc + (bl)     * NCOEF);
        const ulonglong2* c1 = (const ulonglong2*)(sc + (bl + 1) * NCOEF);
        unsigned long long a0 = 0ull, a1 = 0ull;
#pragma unroll
        for (int q = 0; q < NCOEF / 2; q++) {
            const ulonglong2 p0 = c0[q];
            const ulonglong2 p1 = c1[q];
            a0 = fma2(U2[2 * q],     p0.x, a0);
            a0 = fma2(U2[2 * q + 1], p0.y, a0);
            a1 = fma2(U2[2 * q],     p1.x, a1);
            a1 = fma2(U2[2 * q + 1], p1.y, a1);
        }
        const int b0 = bbase + bl;
        float2 r0, r1;
        asm("mov.b64 {%0, %1}, %2;" : "=f"(r0.x), "=f"(r0.y) : "l"(a0));
        asm("mov.b64 {%0, %1}, %2;" : "=f"(r1.x), "=f"(r1.y) : "l"(a1));
        out[(size_t)(b0 * OUT_H + h) * OUT_W + w]       = r0;
        out[(size_t)((b0 + 1) * OUT_H + h) * OUT_W + w] = r1;
    }
}

// ---------------------------------------------------------------------------
extern "C" void kernel_launch(void* const* d_in, const int* in_sizes, int n_in,
                              void* d_out, int out_size) {
    const float* theta = (const float*)d_in[0];
    (void)in_sizes; (void)n_in; (void)out_size;

    dim3 grid(OUT_H * OUT_W / 128, 2);
    tps_fused_kernel<<<grid, 128>>>(theta, (float2*)d_out);
}

// round 5
// speedup vs baseline: 1.5878x; 1.0977x over previous
#include <cuda_runtime.h>

// TpsGridGen: theta (64, 50) -> grid (64, 256, 192, 2) fp32
// Fused kernel. Phase A: per-block coefficient solve [W;A] = Li[:,:25]@(theta+P)
//   -- Li staged to SMEM (warp-uniform LDS broadcast; NO LDC: its 8-cyc/SMSP
//      constant-port floor was the R3 bottleneck).
// Phase B: per-pixel RBF eval, packed fma.rn.f32x2, 4 accumulator chains.
// Control-point coords computed by constexpr fn -> folded to immediates.

#define OUT_H 256
#define OUT_W 192
#define NCP   25
#define NB    64
#define NCOEF 28   // 25 RBF + [1, gx, gy] affine

// Control-point coordinates: P_X[k] = ax[k/5], P_Y[k] = ax[k%5], ax = linspace(-1,1,5)
__host__ __device__ constexpr float cpx(int n) { return 0.5f * (float)(n / 5) - 1.0f; }
__host__ __device__ constexpr float cpy(int n) { return 0.5f * (float)(n % 5) - 1.0f; }

// ---------------------------------------------------------------------------
// Compile-time constants (constexpr fp64 Gauss-Jordan w/ pivoting + clog)
// ---------------------------------------------------------------------------
struct TPSConst {
    float li[NCOEF][NCP];
};

constexpr double cfabs(double x) { return x < 0.0 ? -x : x; }

constexpr double clog(double x) {
    int e = 0;
    while (x >= 1.4142135623730951) { x *= 0.5; e++; }
    while (x <  0.7071067811865476) { x *= 2.0; e--; }
    double t  = (x - 1.0) / (x + 1.0);
    double t2 = t * t;
    double p = t, s = 0.0;
    for (int k = 0; k < 27; k++) { s += p / (double)(2 * k + 1); p *= t2; }
    return 2.0 * s + (double)e * 0.6931471805599453094172321214581766;
}

constexpr TPSConst make_tps() {
    TPSConst r{};
    const double ax[5] = {-1.0, -0.5, 0.0, 0.5, 1.0};
    double PX[NCP] = {}, PY[NCP] = {};
    for (int i = 0; i < 5; i++)
        for (int j = 0; j < 5; j++) { PX[i * 5 + j] = ax[i]; PY[i * 5 + j] = ax[j]; }

    double a[28][56] = {};
    for (int i = 0; i < 25; i++)
        for (int j = 0; j < 25; j++) {
            if (i == j) { a[i][j] = 0.0; }
            else {
                double dx = PX[i] - PX[j], dy = PY[i] - PY[j];
                double d2 = dx * dx + dy * dy;
                a[i][j] = d2 * clog(d2);
            }
        }
    for (int i = 0; i < 25; i++) {
        a[i][25] = 1.0; a[i][26] = PX[i]; a[i][27] = PY[i];
        a[25][i] = 1.0; a[26][i] = PX[i]; a[27][i] = PY[i];
    }
    for (int i = 0; i < 28; i++) a[i][28 + i] = 1.0;

    for (int k = 0; k < 28; k++) {
        int piv = k; double best = cfabs(a[k][k]);
        for (int i = k + 1; i < 28; i++) {
            double v = cfabs(a[i][k]);
            if (v > best) { best = v; piv = i; }
        }
        if (piv != k)
            for (int j = 0; j < 56; j++) {
                double tmp = a[k][j]; a[k][j] = a[piv][j]; a[piv][j] = tmp;
            }
        double inv = 1.0 / a[k][k];
        for (int j = 0; j < 56; j++) a[k][j] *= inv;
        for (int i = 0; i < 28; i++) {
            if (i == k) continue;
            double f = a[i][k];
            if (f != 0.0)
                for (int j = 0; j < 56; j++) a[i][j] -= f * a[k][j];
        }
    }
    for (int n = 0; n < NCOEF; n++)
        for (int m = 0; m < NCP; m++)
            r.li[n][m] = (float)a[n][28 + m];
    return r;
}

// Transposed + lane-duplicated Li, in GLOBAL memory (staged to smem per block).
// v[m][part][j] = dup(li[part*7+j][m]); j padded to 8 -> 6400 B total.
struct alignas(16) TPSLi2 { float2 v[NCP][4][8]; };

constexpr TPSLi2 make_li2() {
    TPSLi2 r{};
    TPSConst t = make_tps();
    for (int m = 0; m < NCP; m++)
        for (int part = 0; part < 4; part++)
            for (int j = 0; j < 7; j++) {
                float v = t.li[part * 7 + j][m];
                r.v[m][part][j] = float2{v, v};
            }
    return r;
}

__device__ const TPSLi2 g_li2 = make_li2();

// ---------------------------------------------------------------------------
// Packed f32x2 helpers
// ---------------------------------------------------------------------------
__device__ __forceinline__ unsigned long long pack2(float lo, float hi) {
    unsigned long long r;
    asm("mov.b64 %0, {%1, %2};" : "=l"(r) : "f"(lo), "f"(hi));
    return r;
}
__device__ __forceinline__ unsigned long long fma2(unsigned long long a,
                                                   unsigned long long b,
                                                   unsigned long long c) {
    unsigned long long d;
    asm("fma.rn.f32x2 %0, %1, %2, %3;" : "=l"(d) : "l"(a), "l"(b), "l"(c));
    return d;
}

// ---------------------------------------------------------------------------
// Fused kernel. grid (384, 2), block 128, 5 blocks/SM.
// Each thread: 1 pixel x 32 batches.
// ---------------------------------------------------------------------------
__global__ __launch_bounds__(128, 5) void tps_fused_kernel(
    const float* __restrict__ theta, float2* __restrict__ out) {

    // s_dyn: theta floats (32x50 = 6.4 KB) during the solve, then coef pairs
    // (32x28 float2 = 7.2 KB). s_li: staged Li table (6.4 KB), persistent.
    __shared__ __align__(16) float  s_dyn[32 * NCOEF * 2];
    __shared__ __align__(16) float2 s_li[NCP * 4 * 8];

    const int tid   = threadIdx.x;
    const int half  = blockIdx.y;          // which 32-batch half
    const int bbase = half * 32;

    // ---- Stage theta (1600 floats) + Li (400 float4) coalesced ----
    {
        const float4* tsrc = (const float4*)(theta + half * 32 * 2 * NCP);
        const float4* lsrc = (const float4*)&g_li2;
        float4* tdst = (float4*)s_dyn;
        float4* ldst = (float4*)s_li;
        for (int i = tid; i < 400; i += 128) {
            tdst[i] = tsrc[i];
            ldst[i] = lsrc[i];
        }
    }
    __syncthreads();

    // ---- Phase A: coef solve. lane = batch, warp = coef quarter ----
    unsigned long long acc[7];
    {
        const int b    = tid & 31;         // lane -> batch
        const int part = tid >> 5;         // warp -> coef quarter (uniform)
#pragma unroll
        for (int j = 0; j < 7; j++) acc[j] = 0ull;
        const float* trow = s_dyn + b * (2 * NCP);
#pragma unroll
        for (int m = 0; m < NCP; m++) {
            const unsigned long long q2 =
                pack2(trow[m] + cpx(m), trow[NCP + m] + cpy(m));
            const unsigned long long* lrow =
                (const unsigned long long*)(s_li + (m * 4 + part) * 8);
#pragma unroll
            for (int j = 0; j < 7; j++)
                acc[j] = fma2(lrow[j], q2, acc[j]);   // LDS broadcast
        }
    }

    // ---- Per-pixel RBF vector (no smem dependence) ----
    const int pid = blockIdx.x * 128 + tid;
    const int h = pid / OUT_W;
    const int w = pid - h * OUT_W;

    const float gx = (w == OUT_W - 1) ? 1.0f
                     : (float)(-1.0 + (double)w * (2.0 / (double)(OUT_W - 1)));
    const float gy = (h == OUT_H - 1) ? 1.0f
                     : (float)(-1.0 + (double)h * (2.0 / (double)(OUT_H - 1)));

    unsigned long long U2[NCOEF];
#pragma unroll
    for (int n = 0; n < NCP; n++) {
        const float dx = gx - cpx(n);
        const float dy = gy - cpy(n);
        const float d2 = dx * dx + dy * dy;
        const float u = (d2 == 0.0f) ? 0.0f : d2 * __logf(d2);
        U2[n] = pack2(u, u);
    }
    U2[25] = pack2(1.0f, 1.0f);
    U2[26] = pack2(gx, gx);
    U2[27] = pack2(gy, gy);

    __syncthreads();   // all theta reads complete before s_dyn is repurposed

    {
        const int b    = tid & 31;
        const int part = tid >> 5;
        unsigned long long* dst =
            (unsigned long long*)((float2*)s_dyn + b * NCOEF + part * 7);
#pragma unroll
        for (int j = 0; j < 7; j++) dst[j] = acc[j];
    }
    __syncthreads();   // coefs visible

    // ---- Phase B: accumulate 32 batches, 4 chains at a time ----
    const float2* sc = (const float2*)s_dyn;
    for (int bl = 0; bl < 32; bl += 4) {
        const ulonglong2* c0 = (const ulonglong2*)(sc + (bl)     * NCOEF);
        const ulonglong2* c1 = (const ulonglong2*)(sc + (bl + 1) * NCOEF);
        const ulonglong2* c2 = (const ulonglong2*)(sc + (bl + 2) * NCOEF);
        const ulonglong2* c3 = (const ulonglong2*)(sc + (bl + 3) * NCOEF);
        unsigned long long a0 = 0ull, a1 = 0ull, a2 = 0ull, a3 = 0ull;
#pragma unroll
        for (int q = 0; q < NCOEF / 2; q++) {
            const ulonglong2 p0 = c0[q];
            const ulonglong2 p1 = c1[q];
            const ulonglong2 p2 = c2[q];
            const ulonglong2 p3 = c3[q];
            a0 = fma2(U2[2 * q],     p0.x, a0);
            a0 = fma2(U2[2 * q + 1], p0.y, a0);
            a1 = fma2(U2[2 * q],     p1.x, a1);
            a1 = fma2(U2[2 * q + 1], p1.y, a1);
            a2 = fma2(U2[2 * q],     p2.x, a2);
            a2 = fma2(U2[2 * q + 1], p2.y, a2);
            a3 = fma2(U2[2 * q],     p3.x, a3);
            a3 = fma2(U2[2 * q + 1], p3.y, a3);
        }
        const int b0 = bbase + bl;
        float2 r0, r1, r2, r3;
        asm("mov.b64 {%0, %1}, %2;" : "=f"(r0.x), "=f"(r0.y) : "l"(a0));
        asm("mov.b64 {%0, %1}, %2;" : "=f"(r1.x), "=f"(r1.y) : "l"(a1));
        asm("mov.b64 {%0, %1}, %2;" : "=f"(r2.x), "=f"(r2.y) : "l"(a2));
        asm("mov.b64 {%0, %1}, %2;" : "=f"(r3.x), "=f"(r3.y) : "l"(a3));
        out[(size_t)((b0)     * OUT_H + h) * OUT_W + w] = r0;
        out[(size_t)((b0 + 1) * OUT_H + h) * OUT_W + w] = r1;
        out[(size_t)((b0 + 2) * OUT_H + h) * OUT_W + w] = r2;
        out[(size_t)((b0 + 3) * OUT_H + h) * OUT_W + w] = r3;
    }
}

// ---------------------------------------------------------------------------
extern "C" void kernel_launch(void* const* d_in, const int* in_sizes, int n_in,
                              void* d_out, int out_size) {
    const float* theta = (const float*)d_in[0];
    (void)in_sizes; (void)n_in; (void)out_size;

    dim3 grid(OUT_H * OUT_W / 128, 2);
    tps_fused_kernel<<<grid, 128>>>(theta, (float2*)d_out);
}